// round 2
// baseline (speedup 1.0000x reference)
#include <cuda_runtime.h>
#include <math.h>

// Problem constants
#define BB 16
#define HH 16
#define NN 577
#define DD 64
#define CC 1024
#define MTOK (BB*NN)            // 9232
#define PLANE (BB*HH*NN*DD)     // 9,453,568 floats per q/k/v plane
#define OUT_ELEMS (MTOK*CC)     // 9,453,568
#define CTA_OFS OUT_ELEMS
#define CTL_OFS (OUT_ELEMS + MTOK)
#define QSCALE 0.125f           // 1/sqrt(64)

// Scratch (device globals: allocation-free per harness rules)
__device__ float g_qkv[3u * PLANE];       // [3][B][H][N][D], q pre-scaled
__device__ float g_attn[OUT_ELEMS];       // [B][N][C] attention output
__device__ float g_cls_logits[BB*HH*NN];  // per-head CLS-row logits
__device__ float g_cls_max[BB*HH];
__device__ float g_cls_den[BB*HH];

// ---------------------------------------------------------------------------
// Tiled fp32 GEMM: C[m,n] = sum_k A[m,k] * W[n,k]  (+bias)
// A row-major [M,K], W row-major [N,K]  ("NT" layout — both K-contiguous)
// mode 1: QKV epilogue -> scatter into g_qkv (q scaled)
// mode 2: A taken from g_attn, plain epilogue into Cout
// BM=BN=128, BK=8, 256 threads, 8x8 per-thread microtile
// ---------------------------------------------------------------------------
__global__ __launch_bounds__(256) void sgemm_nt(
    const float* __restrict__ A, const float* __restrict__ W,
    const float* __restrict__ bias, float* __restrict__ Cout,
    int M, int N, int K, int mode)
{
    __shared__ float As[8][132];
    __shared__ float Ws[8][132];

    const float* Abase = (mode == 2) ? g_attn : A;

    const int tid = threadIdx.x;
    const int bm  = blockIdx.y * 128;
    const int bn  = blockIdx.x * 128;
    const int lr  = tid >> 1;          // 0..127 tile row for loads
    const int lc  = (tid & 1) << 2;    // 0 or 4 (float4 column)
    const int tx  = tid & 15;
    const int ty  = tid >> 4;

    const int arow = (bm + lr < M) ? (bm + lr) : (M - 1);
    const bool avalid = (bm + lr) < M;
    const float* Ap = Abase + (size_t)arow * K + lc;
    const float* Wp = W + (size_t)(bn + lr) * K + lc;

    float acc[8][8];
    #pragma unroll
    for (int i = 0; i < 8; i++)
        #pragma unroll
        for (int j = 0; j < 8; j++) acc[i][j] = 0.f;

    for (int k0 = 0; k0 < K; k0 += 8) {
        float4 av = avalid ? *(const float4*)(Ap + k0) : make_float4(0.f,0.f,0.f,0.f);
        float4 wv = *(const float4*)(Wp + k0);
        __syncthreads();
        As[lc+0][lr] = av.x; As[lc+1][lr] = av.y; As[lc+2][lr] = av.z; As[lc+3][lr] = av.w;
        Ws[lc+0][lr] = wv.x; Ws[lc+1][lr] = wv.y; Ws[lc+2][lr] = wv.z; Ws[lc+3][lr] = wv.w;
        __syncthreads();
        #pragma unroll
        for (int kk = 0; kk < 8; kk++) {
            float a[8], b[8];
            *(float4*)&a[0] = *(const float4*)&As[kk][ty*8];
            *(float4*)&a[4] = *(const float4*)&As[kk][ty*8+4];
            *(float4*)&b[0] = *(const float4*)&Ws[kk][tx*8];
            *(float4*)&b[4] = *(const float4*)&Ws[kk][tx*8+4];
            #pragma unroll
            for (int i = 0; i < 8; i++)
                #pragma unroll
                for (int j = 0; j < 8; j++)
                    acc[i][j] += a[i] * b[j];
        }
    }

    if (mode == 1) {
        // QKV scatter: n -> (which, h, d); m -> (b, tok)
        #pragma unroll
        for (int i = 0; i < 8; i++) {
            int m = bm + ty*8 + i;
            if (m >= M) continue;
            int b_ = m / NN;
            int tok = m - b_ * NN;
            #pragma unroll
            for (int j = 0; j < 8; j++) {
                int n = bn + tx*8 + j;
                float v = acc[i][j] + bias[n];
                int which = n >> 10;          // /1024
                int rest  = n & 1023;
                int h = rest >> 6;
                int d = rest & 63;
                if (which == 0) v *= QSCALE;
                g_qkv[(size_t)which * PLANE + (((size_t)(b_*HH + h) * NN + tok) << 6) + d] = v;
            }
        }
    } else {
        #pragma unroll
        for (int i = 0; i < 8; i++) {
            int m = bm + ty*8 + i;
            if (m >= M) continue;
            #pragma unroll
            for (int j = 0; j < 8; j++) {
                int n = bn + tx*8 + j;
                Cout[(size_t)m * N + n] = acc[i][j] + bias[n];
            }
        }
    }
}

// ---------------------------------------------------------------------------
// Flash attention: grid (q_tiles=10, BH=256), 256 threads.
// BQ=64 queries, key tiles of 64. Thread t: query row r=t/4, dims d0=(t%4)*16.
// smem rows padded to 68 floats (bank-conflict-free, float4-aligned).
// ---------------------------------------------------------------------------
#define SROW 68
#define FLASH_SMEM (4 * 64 * SROW * 4)

__global__ __launch_bounds__(256) void flash_attn_kernel()
{
    extern __shared__ float sm[];
    float* Qs = sm;
    float* Ks = sm + 64*SROW;
    float* Vs = sm + 2*64*SROW;
    float* Ps = sm + 3*64*SROW;

    const int tid = threadIdx.x;
    const int qt  = blockIdx.x;     // 0..9
    const int bh  = blockIdx.y;     // 0..255
    const int q0g = qt * 64;

    const float* Qg = g_qkv + (size_t)bh * NN * DD;
    const float* Kg = g_qkv + (size_t)PLANE + (size_t)bh * NN * DD;
    const float* Vg = g_qkv + 2u*(size_t)PLANE + (size_t)bh * NN * DD;

    // load Q tile (zero-pad invalid rows)
    #pragma unroll
    for (int i = 0; i < 4; i++) {
        int p = i*256 + tid;       // float4 index, 1024 total
        int row = p >> 4;
        int c4  = (p & 15) << 2;
        float4 v = (q0g + row < NN) ? *(const float4*)(Qg + (size_t)(q0g+row)*DD + c4)
                                    : make_float4(0.f,0.f,0.f,0.f);
        *(float4*)(Qs + row*SROW + c4) = v;
    }

    const int r  = tid >> 2;       // query row in tile
    const int l4 = tid & 3;
    const int d0 = l4 * 16;

    float acc[16];
    #pragma unroll
    for (int i = 0; i < 16; i++) acc[i] = 0.f;
    float m_i = -1e30f, l_i = 0.f;

    for (int kt = 0; kt < 10; kt++) {
        const int k0g = kt * 64;
        __syncthreads();  // previous tile's Ps/Vs consumption done (also covers Q tile)
        #pragma unroll
        for (int i = 0; i < 4; i++) {
            int p = i*256 + tid;
            int row = p >> 4;
            int c4  = (p & 15) << 2;
            bool ok = (k0g + row) < NN;
            float4 kv = ok ? *(const float4*)(Kg + (size_t)(k0g+row)*DD + c4) : make_float4(0.f,0.f,0.f,0.f);
            float4 vv = ok ? *(const float4*)(Vg + (size_t)(k0g+row)*DD + c4) : make_float4(0.f,0.f,0.f,0.f);
            *(float4*)(Ks + row*SROW + c4) = kv;
            *(float4*)(Vs + row*SROW + c4) = vv;
        }
        __syncthreads();

        // S: 16 keys per thread (j = l4 + 4*jj)
        float s[16];
        #pragma unroll
        for (int jj = 0; jj < 16; jj++) s[jj] = 0.f;
        #pragma unroll
        for (int d4 = 0; d4 < 64; d4 += 4) {
            float4 q4 = *(const float4*)(Qs + r*SROW + d4);
            #pragma unroll
            for (int jj = 0; jj < 16; jj++) {
                int j = l4 + (jj << 2);
                float4 k4 = *(const float4*)(Ks + j*SROW + d4);
                s[jj] += q4.x*k4.x + q4.y*k4.y + q4.z*k4.z + q4.w*k4.w;
            }
        }

        // mask + row max (reduce over 4 lanes of this row)
        float mloc = -1e30f;
        #pragma unroll
        for (int jj = 0; jj < 16; jj++) {
            int jg = k0g + l4 + (jj << 2);
            if (jg >= NN) s[jj] = -1e30f;
            mloc = fmaxf(mloc, s[jj]);
        }
        mloc = fmaxf(mloc, __shfl_xor_sync(0xffffffffu, mloc, 1));
        mloc = fmaxf(mloc, __shfl_xor_sync(0xffffffffu, mloc, 2));
        float m_new = fmaxf(m_i, mloc);
        float alpha = __expf(m_i - m_new);

        float psum = 0.f;
        #pragma unroll
        for (int jj = 0; jj < 16; jj++) {
            float pv = (s[jj] > -1e29f) ? __expf(s[jj] - m_new) : 0.f;
            psum += pv;
            Ps[r*SROW + l4 + (jj << 2)] = pv;
        }
        psum += __shfl_xor_sync(0xffffffffu, psum, 1);
        psum += __shfl_xor_sync(0xffffffffu, psum, 2);
        l_i = l_i * alpha + psum;
        m_i = m_new;
        #pragma unroll
        for (int i = 0; i < 16; i++) acc[i] *= alpha;
        __syncthreads();  // Ps visible

        // O += P @ V (thread's 16 dims, all 64 keys)
        #pragma unroll
        for (int j = 0; j < 64; j++) {
            float pv = Ps[r*SROW + j];
            const float* vrow = Vs + j*SROW + d0;
            float4 v0 = *(const float4*)(vrow);
            float4 v1 = *(const float4*)(vrow + 4);
            float4 v2 = *(const float4*)(vrow + 8);
            float4 v3 = *(const float4*)(vrow + 12);
            acc[0]  += pv*v0.x; acc[1]  += pv*v0.y; acc[2]  += pv*v0.z; acc[3]  += pv*v0.w;
            acc[4]  += pv*v1.x; acc[5]  += pv*v1.y; acc[6]  += pv*v1.z; acc[7]  += pv*v1.w;
            acc[8]  += pv*v2.x; acc[9]  += pv*v2.y; acc[10] += pv*v2.z; acc[11] += pv*v2.w;
            acc[12] += pv*v3.x; acc[13] += pv*v3.y; acc[14] += pv*v3.z; acc[15] += pv*v3.w;
        }
    }

    const int qg = q0g + r;
    if (qg < NN) {
        float inv = 1.f / l_i;
        int b_ = bh >> 4, h = bh & 15;
        float* o = g_attn + ((size_t)b_ * NN + qg) * CC + h * DD + d0;
        #pragma unroll
        for (int i = 0; i < 16; i += 4) {
            float4 v = make_float4(acc[i]*inv, acc[i+1]*inv, acc[i+2]*inv, acc[i+3]*inv);
            *(float4*)(o + i) = v;
        }
    }
}

// ---------------------------------------------------------------------------
// CLS-row logits per (b,h): logits[m] = q0 . k[m]; also max & softmax denom
// ---------------------------------------------------------------------------
__global__ __launch_bounds__(128) void cls_logits_kernel()
{
    __shared__ float q0s[64];
    __shared__ float red[128];
    const int bh  = blockIdx.x;
    const int tid = threadIdx.x;
    const float* Qg = g_qkv + (size_t)bh * NN * DD;            // q already scaled
    const float* Kg = g_qkv + (size_t)PLANE + (size_t)bh * NN * DD;

    if (tid < 64) q0s[tid] = Qg[tid];
    __syncthreads();

    float lg[5];
    float mloc = -1e30f;
    #pragma unroll
    for (int i = 0; i < 5; i++) {
        int m = tid + i*128;
        float s = -1e30f;
        if (m < NN) {
            s = 0.f;
            const float* kr = Kg + (size_t)m * DD;
            #pragma unroll
            for (int d4 = 0; d4 < 64; d4 += 4) {
                float4 k4 = *(const float4*)(kr + d4);
                s += q0s[d4]*k4.x + q0s[d4+1]*k4.y + q0s[d4+2]*k4.z + q0s[d4+3]*k4.w;
            }
            g_cls_logits[(size_t)bh * NN + m] = s;
        }
        lg[i] = s;
        mloc = fmaxf(mloc, s);
    }

    red[tid] = mloc; __syncthreads();
    for (int o = 64; o > 0; o >>= 1) {
        if (tid < o) red[tid] = fmaxf(red[tid], red[tid+o]);
        __syncthreads();
    }
    float mx = red[0];
    __syncthreads();

    float se = 0.f;
    #pragma unroll
    for (int i = 0; i < 5; i++)
        if (lg[i] > -1e29f) se += __expf(lg[i] - mx);
    red[tid] = se; __syncthreads();
    for (int o = 64; o > 0; o >>= 1) {
        if (tid < o) red[tid] += red[tid+o];
        __syncthreads();
    }
    if (tid == 0) { g_cls_max[bh] = mx; g_cls_den[bh] = red[0]; }
}

// Head-mean of CLS logits and CLS attention
__global__ void cls_out_kernel(float* __restrict__ out_cta, float* __restrict__ out_ctl)
{
    int idx = blockIdx.x * blockDim.x + threadIdx.x;
    if (idx >= MTOK) return;
    int b_ = idx / NN;
    int m  = idx - b_ * NN;
    float sl = 0.f, sa = 0.f;
    #pragma unroll
    for (int h = 0; h < HH; h++) {
        int bh = b_ * HH + h;
        float l = g_cls_logits[(size_t)bh * NN + m];
        sl += l;
        sa += __expf(l - g_cls_max[bh]) / g_cls_den[bh];
    }
    out_ctl[idx] = sl * (1.f / 16.f);
    out_cta[idx] = sa * (1.f / 16.f);
}

// ---------------------------------------------------------------------------
extern "C" void kernel_launch(void* const* d_in, const int* in_sizes, int n_in,
                              void* d_out, int out_size)
{
    const float* x      = (const float*)d_in[0];
    const float* w_qkv  = (const float*)d_in[1];
    const float* b_qkv  = (const float*)d_in[2];
    const float* w_proj = (const float*)d_in[3];
    const float* b_proj = (const float*)d_in[4];
    float* out = (float*)d_out;

    // 1) QKV projection + scatter (q scaled)
    {
        dim3 grid(3*CC/128, (MTOK + 127) / 128);
        sgemm_nt<<<grid, 256>>>(x, w_qkv, b_qkv, nullptr, MTOK, 3*CC, CC, 1);
    }

    // 2) Flash attention
    cudaFuncSetAttribute(flash_attn_kernel,
                         cudaFuncAttributeMaxDynamicSharedMemorySize, FLASH_SMEM);
    {
        dim3 grid(10, BB*HH);
        flash_attn_kernel<<<grid, 256, FLASH_SMEM>>>();
    }

    // 3) CLS-row outputs
    cls_logits_kernel<<<BB*HH, 128>>>();
    cls_out_kernel<<<(MTOK + 255) / 256, 256>>>(out + CTA_OFS, out + CTL_OFS);

    // 4) Output projection
    {
        dim3 grid(CC/128, (MTOK + 127) / 128);
        sgemm_nt<<<grid, 256>>>(nullptr, w_proj, b_proj, out, MTOK, CC, CC, 2);
    }
}